// round 14
// baseline (speedup 1.0000x reference)
#include <cuda_runtime.h>
#include <cuda_bf16.h>
#include <cuda_fp16.h>
#include <cstdint>

#define N_NODES 50000
#define N_EDGES 625000
#define F 128
#define SCAN_BLOCKS 49          // 49 * 1024 = 50176 >= N_NODES
#define TILE_M 64
#define GEMM_BLOCKS ((N_NODES + TILE_M - 1) / TILE_M)   // 782
#define GEMM_THREADS 256
#define SPAD 136                // padded row stride (bf16 elems) -> conflict-free LDSM
#define TILE_A_BYTES (64 * SPAD * 2)                    // 17408
#define TILE_B_BYTES (128 * SPAD * 2)                   // 34816
#define GEMM_SMEM (2 * TILE_A_BYTES + 2 * TILE_B_BYTES) // 104448 -> 2 CTAs/SM
#define AGG_FLAG (1 << 30)

// ---------------------------------------------------------------------------
// Scratch (__device__ globals => allocation-free)
// Invariant: g_count[] == 0 at entry of every kernel_launch call
// (zero-init at load; fused scatter's atomicSub cursor restores it each call).
// ---------------------------------------------------------------------------
__device__ __half        g_support[(size_t)N_NODES * F]; // x @ W, fp16 (12.8 MB)
__device__ int           g_count[N_NODES];               // histogram / cursor
__device__ int           g_start[N_NODES + 1];           // CSR row starts
__device__ int2          g_edge[N_EDGES];                // packed {col, val} by row
__device__ int           g_agg[SCAN_BLOCKS];             // lookback aggregates
__device__ __nv_bfloat16 g_wt_hi[F * F];                 // W^T hi (bf16), [n][k]
__device__ __nv_bfloat16 g_wt_lo[F * F];                 // W^T lo (bf16), [n][k]

__device__ __forceinline__ uint32_t smem_u32(const void* p) {
    uint32_t a;
    asm("{ .reg .u64 t; cvta.to.shared.u64 t, %1; cvt.u32.u64 %0, t; }" : "=r"(a) : "l"(p));
    return a;
}

#define LDSM4(r0, r1, r2, r3, addr)                                              \
    asm volatile("ldmatrix.sync.aligned.m8n8.x4.shared.b16 {%0,%1,%2,%3}, [%4];" \
                 : "=r"(r0), "=r"(r1), "=r"(r2), "=r"(r3) : "r"(addr))

#define MMA16816(c, a0, a1, a2, a3, b0, b1)                                      \
    asm volatile("mma.sync.aligned.m16n8k16.row.col.f32.bf16.bf16.f32 "          \
                 "{%0,%1,%2,%3}, {%4,%5,%6,%7}, {%8,%9}, {%0,%1,%2,%3};"         \
                 : "+f"((c)[0]), "+f"((c)[1]), "+f"((c)[2]), "+f"((c)[3])        \
                 : "r"(a0), "r"(a1), "r"(a2), "r"(a3), "r"(b0), "r"(b1))

// ---------------------------------------------------------------------------
// Kernel 1: histogram + W^T hi/lo split + lookback-flag reset
// ---------------------------------------------------------------------------
__global__ void hist_kernel(const int* __restrict__ rows, const float* __restrict__ w) {
    const int gid = blockIdx.x * blockDim.x + threadIdx.x;
    if (gid < N_EDGES) atomicAdd(&g_count[rows[gid]], 1);
    if (gid < SCAN_BLOCKS) g_agg[gid] = 0;
    if (gid < F * F) {
        // gid = n*F + k ; W stored [k][n]
        int n = gid >> 7, k = gid & 127;
        float v = w[k * F + n];
        __nv_bfloat16 h = __float2bfloat16(v);
        g_wt_hi[gid] = h;
        g_wt_lo[gid] = __float2bfloat16(v - __bfloat162float(h));
    }
}

// ---------------------------------------------------------------------------
// Kernel 2: single-pass exclusive scan of g_count -> g_start
// 49 co-resident blocks; decoupled lookback, full-predecessor stride.
// ---------------------------------------------------------------------------
__global__ __launch_bounds__(1024) void scan_fused_kernel() {
    __shared__ int wsum[32];
    __shared__ int blk_prev;
    const int t    = threadIdx.x;
    const int bid  = blockIdx.x;
    const int lane = t & 31;
    const int wid  = t >> 5;
    const int idx  = bid * 1024 + t;

    const int v = (idx < N_NODES) ? g_count[idx] : 0;

    int s = v;
    #pragma unroll
    for (int off = 1; off < 32; off <<= 1) {
        int n = __shfl_up_sync(0xffffffffu, s, off);
        if (lane >= off) s += n;
    }
    if (lane == 31) wsum[wid] = s;
    __syncthreads();

    if (wid == 0) {
        int ws = wsum[lane];
        #pragma unroll
        for (int off = 1; off < 32; off <<= 1) {
            int n = __shfl_up_sync(0xffffffffu, ws, off);
            if (lane >= off) ws += n;
        }
        wsum[lane] = ws;
        if (lane == 31) atomicExch(&g_agg[bid], ws | AGG_FLAG);

        int a = 0;
        for (int p = lane; p < bid; p += 32) {
            volatile int* agg = g_agg;
            int xv;
            do { xv = agg[p]; } while (!(xv & AGG_FLAG));
            a += xv & (AGG_FLAG - 1);
        }
        #pragma unroll
        for (int off = 16; off >= 1; off >>= 1)
            a += __shfl_xor_sync(0xffffffffu, a, off);
        if (lane == 0) blk_prev = a;
    }
    __syncthreads();

    const int wexcl = (wid > 0) ? wsum[wid - 1] : 0;
    if (idx < N_NODES) g_start[idx] = blk_prev + wexcl + (s - v);
    if (idx == 0) g_start[N_NODES] = N_EDGES;
}

// ---------------------------------------------------------------------------
// Kernel 3: GEMM (HMMA bf16 split-3, 64x128 tile, 2 CTAs/SM)
//           + POST-epilogue fused CSR scatter (overlaps other CTAs' MMA)
// 256 threads; warp w: rows [16*(w>>1), +16), cols [64*(w&1), +64).
// ---------------------------------------------------------------------------
__global__ __launch_bounds__(GEMM_THREADS, 2)
void gemm_scatter_kernel(const float* __restrict__ x,
                         const int*   __restrict__ rows,
                         const int*   __restrict__ cols,
                         const float* __restrict__ vals) {
    extern __shared__ char smem[];
    __nv_bfloat16* sAh = (__nv_bfloat16*)smem;                 // 64 x SPAD
    __nv_bfloat16* sAl = sAh + 64 * SPAD;
    __nv_bfloat16* sBh = sAl + 64 * SPAD;                      // 128 x SPAD
    __nv_bfloat16* sBl = sBh + 128 * SPAD;

    const int t  = threadIdx.x;
    const int m0 = blockIdx.x * TILE_M;

    // ---- Load + split x tile into smem (hi/lo bf16), padded stride ----
    #pragma unroll 4
    for (int i = 0; i < 8; i++) {
        int idx = t + GEMM_THREADS * i;        // 2048 float4 slots (64 rows x 32)
        int row = idx >> 5;
        int c4  = (idx & 31) * 4;
        int m   = m0 + row;
        float4 xv = (m < N_NODES) ? ((const float4*)x)[((size_t)m * F + c4) >> 2]
                                  : make_float4(0.f, 0.f, 0.f, 0.f);
        __nv_bfloat16 h0 = __float2bfloat16(xv.x);
        __nv_bfloat16 h1 = __float2bfloat16(xv.y);
        __nv_bfloat16 h2 = __float2bfloat16(xv.z);
        __nv_bfloat16 h3 = __float2bfloat16(xv.w);
        __nv_bfloat16 l0 = __float2bfloat16(xv.x - __bfloat162float(h0));
        __nv_bfloat16 l1 = __float2bfloat16(xv.y - __bfloat162float(h1));
        __nv_bfloat16 l2 = __float2bfloat16(xv.z - __bfloat162float(h2));
        __nv_bfloat16 l3 = __float2bfloat16(xv.w - __bfloat162float(h3));
        uint2 hi, lo;
        hi.x = (uint32_t)__bfloat16_as_ushort(h0) | ((uint32_t)__bfloat16_as_ushort(h1) << 16);
        hi.y = (uint32_t)__bfloat16_as_ushort(h2) | ((uint32_t)__bfloat16_as_ushort(h3) << 16);
        lo.x = (uint32_t)__bfloat16_as_ushort(l0) | ((uint32_t)__bfloat16_as_ushort(l1) << 16);
        lo.y = (uint32_t)__bfloat16_as_ushort(l2) | ((uint32_t)__bfloat16_as_ushort(l3) << 16);
        int off = row * SPAD + c4;
        *(uint2*)&sAh[off] = hi;
        *(uint2*)&sAl[off] = lo;
    }

    // ---- Copy pre-split W^T (bf16) into smem, padded stride ----
    // 128 rows x 16 uint4 slots = 2048 slots; 256 threads -> 8 iterations.
    // (R12 bug: iterated 16x, overrunning g_wt_* reads and smem writes.)
    #pragma unroll 4
    for (int i = 0; i < 8; i++) {
        int idx = t + GEMM_THREADS * i;        // 2048 uint4 slots
        int n   = idx >> 4;
        int c8  = (idx & 15) * 8;
        int off = n * SPAD + c8;
        *(uint4*)&sBh[off] = *(const uint4*)&g_wt_hi[n * F + c8];
        *(uint4*)&sBl[off] = *(const uint4*)&g_wt_lo[n * F + c8];
    }
    __syncthreads();

    const int wid  = t >> 5;
    const int lane = t & 31;
    const int R    = (wid >> 1) * 16;          // row base within tile (0..48)
    const int C0   = (wid & 1) * 64;           // col base

    float acc[8][4];
    #pragma unroll
    for (int i = 0; i < 8; i++)
        #pragma unroll
        for (int j = 0; j < 4; j++) acc[i][j] = 0.f;

    const uint32_t base   = smem_u32(smem);
    const uint32_t aHbase = base;
    const uint32_t aLbase = base + TILE_A_BYTES;
    const uint32_t bHbase = base + 2 * TILE_A_BYTES;
    const uint32_t bLbase = base + 2 * TILE_A_BYTES + TILE_B_BYTES;

    const int arow    = R + (lane & 7) + ((lane >> 3) & 1) * 8;
    const int acolh   = (lane >> 4) * 8;
    const int brow_in = (lane & 7) + ((lane >= 16) ? 8 : 0);
    const int bcolh   = ((lane >> 3) & 1) * 8;

    #pragma unroll 1
    for (int kc = 0; kc < 8; kc++) {
        const int k0 = kc * 16;
        const uint32_t aoff = (uint32_t)((arow * SPAD + k0 + acolh) * 2);
        uint32_t ah0, ah1, ah2, ah3, al0, al1, al2, al3;
        LDSM4(ah0, ah1, ah2, ah3, aHbase + aoff);
        LDSM4(al0, al1, al2, al3, aLbase + aoff);

        #pragma unroll
        for (int np = 0; np < 4; np++) {
            const int ncol = C0 + np * 16;
            const uint32_t boff = (uint32_t)(((ncol + brow_in) * SPAD + k0 + bcolh) * 2);
            uint32_t bh0, bh1, bh2, bh3, bl0, bl1, bl2, bl3;
            LDSM4(bh0, bh1, bh2, bh3, bHbase + boff);
            LDSM4(bl0, bl1, bl2, bl3, bLbase + boff);
            MMA16816(acc[2 * np],     ah0, ah1, ah2, ah3, bh0, bh1);
            MMA16816(acc[2 * np + 1], ah0, ah1, ah2, ah3, bh2, bh3);
            MMA16816(acc[2 * np],     ah0, ah1, ah2, ah3, bl0, bl1);
            MMA16816(acc[2 * np + 1], ah0, ah1, ah2, ah3, bl2, bl3);
            MMA16816(acc[2 * np],     al0, al1, al2, al3, bh0, bh1);
            MMA16816(acc[2 * np + 1], al0, al1, al2, al3, bh2, bh3);
        }
    }

    // ---- Epilogue: accum regs -> g_support as fp16 (half2 per 2 cols) ----
    const int g   = lane >> 2;
    const int tig = lane & 3;
    const int m1  = m0 + R + g;
    const int m2  = m1 + 8;
    #pragma unroll
    for (int nt = 0; nt < 8; nt++) {
        const int c = C0 + nt * 8 + tig * 2;
        if (m1 < N_NODES)
            *(__half2*)&g_support[(size_t)m1 * F + c] = __floats2half2_rn(acc[nt][0], acc[nt][1]);
        if (m2 < N_NODES)
            *(__half2*)&g_support[(size_t)m2 * F + c] = __floats2half2_rn(acc[nt][2], acc[nt][3]);
    }

    // ---- POST-epilogue fused scatter: overlapped with other CTAs' MMA ----
    for (int e = blockIdx.x * GEMM_THREADS + t; e < N_EDGES;
         e += GEMM_BLOCKS * GEMM_THREADS) {
        int r = rows[e];
        int p = g_start[r] + atomicSub(&g_count[r], 1) - 1;
        g_edge[p] = make_int2(cols[e], __float_as_int(vals[e]));
    }
}

// ---------------------------------------------------------------------------
// Kernel 4: CSR SpMM. Warp per row; HALF-warp per edge (uint4 = 8 halves per
// lane), 2-pair unroll; fp32 accumulation; cross-half shfl reduction; bias in
// half 0 only.
// ---------------------------------------------------------------------------
__device__ __forceinline__ void fma_half8(float* acc, float v, uint4 u) {
    const float2 f0 = __half22float2(*reinterpret_cast<__half2*>(&u.x));
    const float2 f1 = __half22float2(*reinterpret_cast<__half2*>(&u.y));
    const float2 f2 = __half22float2(*reinterpret_cast<__half2*>(&u.z));
    const float2 f3 = __half22float2(*reinterpret_cast<__half2*>(&u.w));
    acc[0] += v * f0.x; acc[1] += v * f0.y;
    acc[2] += v * f1.x; acc[3] += v * f1.y;
    acc[4] += v * f2.x; acc[5] += v * f2.y;
    acc[6] += v * f3.x; acc[7] += v * f3.y;
}

__global__ __launch_bounds__(256) void spmm_csr_kernel(const float* __restrict__ bias,
                                                       float*       __restrict__ out) {
    const int warp = (blockIdx.x * blockDim.x + threadIdx.x) >> 5;
    const int lane = threadIdx.x & 31;
    if (warp >= N_NODES) return;

    const int half = lane >> 4;        // which edge of the pair
    const int sub  = lane & 15;        // column group: cols [sub*8, +8)

    const int s = g_start[warp];
    const int e = g_start[warp + 1];

    float acc[8];
    if (half == 0) {
        const float4 b0 = *(const float4*)&bias[sub * 8];
        const float4 b1 = *(const float4*)&bias[sub * 8 + 4];
        acc[0] = b0.x; acc[1] = b0.y; acc[2] = b0.z; acc[3] = b0.w;
        acc[4] = b1.x; acc[5] = b1.y; acc[6] = b1.z; acc[7] = b1.w;
    } else {
        #pragma unroll
        for (int j = 0; j < 8; j++) acc[j] = 0.f;
    }

    int base = s;
    for (; base + 4 <= e; base += 4) {            // 4 edges: 2 per half-warp
        const int2 ed0 = g_edge[base + half];
        const int2 ed1 = g_edge[base + 2 + half];
        const uint4 u0 = *(const uint4*)&g_support[(size_t)ed0.x * F + sub * 8];
        const uint4 u1 = *(const uint4*)&g_support[(size_t)ed1.x * F + sub * 8];
        fma_half8(acc, __int_as_float(ed0.y), u0);
        fma_half8(acc, __int_as_float(ed1.y), u1);
    }
    for (; base + 2 <= e; base += 2) {            // one pair
        const int2 ed = g_edge[base + half];
        const uint4 u = *(const uint4*)&g_support[(size_t)ed.x * F + sub * 8];
        fma_half8(acc, __int_as_float(ed.y), u);
    }
    if (base < e && half == 0) {                  // odd tail: half 0 only
        const int2 ed = g_edge[base];
        const uint4 u = *(const uint4*)&g_support[(size_t)ed.x * F + sub * 8];
        fma_half8(acc, __int_as_float(ed.y), u);
    }

    // cross-half reduction: lane l += lane l^16
    #pragma unroll
    for (int j = 0; j < 8; j++)
        acc[j] += __shfl_xor_sync(0xffffffffu, acc[j], 16);

    if (half == 0) {
        float* dst = &out[(size_t)warp * F + sub * 8];
        *(float4*)dst       = make_float4(acc[0], acc[1], acc[2], acc[3]);
        *(float4*)(dst + 4) = make_float4(acc[4], acc[5], acc[6], acc[7]);
    }
}

// ---------------------------------------------------------------------------
// Launch. Inputs: 0=x, 1=weight, 2=bias, 3=edge_vals, 4=edge_rows, 5=edge_cols
// ---------------------------------------------------------------------------
extern "C" void kernel_launch(void* const* d_in, const int* in_sizes, int n_in,
                              void* d_out, int out_size) {
    const float* x    = (const float*)d_in[0];
    const float* w    = (const float*)d_in[1];
    const float* bias = (const float*)d_in[2];
    const float* vals = (const float*)d_in[3];
    const int*   rows = (const int*)d_in[4];
    const int*   cols = (const int*)d_in[5];
    float*       out  = (float*)d_out;

    static bool attr_set = false;
    if (!attr_set) {
        cudaFuncSetAttribute(gemm_scatter_kernel,
                             cudaFuncAttributeMaxDynamicSharedMemorySize, GEMM_SMEM);
        attr_set = true;
    }

    // 1) histogram + W split + flag reset
    hist_kernel<<<(N_EDGES + 255) / 256, 256>>>(rows, w);
    // 2) single-pass scan -> g_start
    scan_fused_kernel<<<SCAN_BLOCKS, 1024>>>();
    // 3) GEMM (support = x @ W, fp16 out) + post-epilogue scatter
    gemm_scatter_kernel<<<GEMM_BLOCKS, GEMM_THREADS, GEMM_SMEM>>>(x, rows, cols, vals);
    // 4) out = A_csr @ support + bias
    {
        const long long threads = (long long)N_NODES * 32;
        spmm_csr_kernel<<<(int)((threads + 255) / 256), 256>>>(bias, out);
    }
}

// round 15
// speedup vs baseline: 1.2946x; 1.2946x over previous
#include <cuda_runtime.h>
#include <cuda_fp16.h>
#include <cstdint>

#define N_NODES 50000
#define N_EDGES 625000
#define F 128
#define SCAN_BLOCKS 49          // 49 * 1024 = 50176 >= N_NODES
#define TILE_M 128
#define GEMM_BLOCKS ((N_NODES + TILE_M - 1) / TILE_M)   // 391
#define GEMM_THREADS 512
#define SPAD 136                // padded row stride (fp16 elems) -> conflict-free LDSM
#define TILE_BYTES (128 * SPAD * 2)                     // 34816
#define GEMM_SMEM (2 * TILE_BYTES)                      // A + B = 69632 -> 2 CTAs/SM
#define AGG_FLAG (1 << 30)

// ---------------------------------------------------------------------------
// Scratch (__device__ globals => allocation-free)
// Invariant: g_count[] == 0 at entry of every kernel_launch call
// (zero-init at load; scatter's atomicSub cursor restores it each call).
// ---------------------------------------------------------------------------
__device__ __half g_support[(size_t)N_NODES * F]; // x @ W, fp16 (12.8 MB)
__device__ int    g_count[N_NODES];               // histogram / cursor
__device__ int    g_start[N_NODES + 1];           // CSR row starts
__device__ int2   g_edge[N_EDGES];                // packed {col, val} by row
__device__ int    g_agg[SCAN_BLOCKS];             // lookback aggregates
__device__ __half g_wt[F * F];                    // W^T (fp16), [n][k]

__device__ __forceinline__ uint32_t smem_u32(const void* p) {
    uint32_t a;
    asm("{ .reg .u64 t; cvta.to.shared.u64 t, %1; cvt.u32.u64 %0, t; }" : "=r"(a) : "l"(p));
    return a;
}

#define LDSM4(r0, r1, r2, r3, addr)                                              \
    asm volatile("ldmatrix.sync.aligned.m8n8.x4.shared.b16 {%0,%1,%2,%3}, [%4];" \
                 : "=r"(r0), "=r"(r1), "=r"(r2), "=r"(r3) : "r"(addr))

#define MMA16816F16(c, a0, a1, a2, a3, b0, b1)                                   \
    asm volatile("mma.sync.aligned.m16n8k16.row.col.f32.f16.f16.f32 "            \
                 "{%0,%1,%2,%3}, {%4,%5,%6,%7}, {%8,%9}, {%0,%1,%2,%3};"         \
                 : "+f"((c)[0]), "+f"((c)[1]), "+f"((c)[2]), "+f"((c)[3])        \
                 : "r"(a0), "r"(a1), "r"(a2), "r"(a3), "r"(b0), "r"(b1))

// ---------------------------------------------------------------------------
// Kernel 1: GEMM (single-term fp16 HMMA, 128x128 tile, 2 CTAs/SM)
//           + fused edge histogram + lookback-flag reset
// 512 threads; warp w: rows [16*(w>>1), +16), cols [64*(w&1), +64).
// ---------------------------------------------------------------------------
__global__ __launch_bounds__(GEMM_THREADS, 2)
void gemm_hist_kernel(const float* __restrict__ x, const int* __restrict__ rows) {
    extern __shared__ char smem[];
    __half* sA = (__half*)smem;                  // 128 x SPAD fp16
    __half* sB = sA + 128 * SPAD;                // 128 x SPAD fp16 (W^T)

    const int t   = threadIdx.x;
    const int m0  = blockIdx.x * TILE_M;
    const int gid = blockIdx.x * GEMM_THREADS + t;

    // ---- Fused: edge-row histogram (overlaps the tile-load latency) ----
    for (int e = gid; e < N_EDGES; e += GEMM_BLOCKS * GEMM_THREADS)
        atomicAdd(&g_count[rows[e]], 1);
    if (gid < SCAN_BLOCKS) g_agg[gid] = 0;

    // ---- Load x tile, convert to fp16, padded stride ----
    #pragma unroll 4
    for (int i = 0; i < 8; i++) {
        int idx = t + GEMM_THREADS * i;          // 4096 float4 slots (128 x 32)
        int row = idx >> 5;
        int c4  = (idx & 31) * 4;
        int m   = m0 + row;
        float4 xv = (m < N_NODES) ? ((const float4*)x)[((size_t)m * F + c4) >> 2]
                                  : make_float4(0.f, 0.f, 0.f, 0.f);
        __half2 p0 = __floats2half2_rn(xv.x, xv.y);
        __half2 p1 = __floats2half2_rn(xv.z, xv.w);
        *(__half2*)&sA[row * SPAD + c4]     = p0;
        *(__half2*)&sA[row * SPAD + c4 + 2] = p1;
    }

    // ---- Copy pre-converted W^T (fp16) into smem, padded stride ----
    // 128 rows x 16 uint4 slots = 2048 slots; 512 threads -> 4 iterations.
    #pragma unroll
    for (int i = 0; i < 4; i++) {
        int idx = t + GEMM_THREADS * i;
        int n   = idx >> 4;
        int c8  = (idx & 15) * 8;
        *(uint4*)&sB[n * SPAD + c8] = *(const uint4*)&g_wt[n * F + c8];
    }
    __syncthreads();

    const int wid  = t >> 5;
    const int lane = t & 31;
    const int R    = (wid >> 1) * 16;            // row base (0..112)
    const int C0   = (wid & 1) * 64;             // col base

    float acc[8][4];
    #pragma unroll
    for (int i = 0; i < 8; i++)
        #pragma unroll
        for (int j = 0; j < 4; j++) acc[i][j] = 0.f;

    const uint32_t aBase = smem_u32(smem);
    const uint32_t bBase = aBase + TILE_BYTES;

    const int arow    = R + (lane & 7) + ((lane >> 3) & 1) * 8;
    const int acolh   = (lane >> 4) * 8;
    const int brow_in = (lane & 7) + ((lane >= 16) ? 8 : 0);
    const int bcolh   = ((lane >> 3) & 1) * 8;

    #pragma unroll 1
    for (int kc = 0; kc < 8; kc++) {
        const int k0 = kc * 16;
        uint32_t a0, a1, a2, a3;
        LDSM4(a0, a1, a2, a3, aBase + (uint32_t)((arow * SPAD + k0 + acolh) * 2));

        #pragma unroll
        for (int np = 0; np < 4; np++) {
            const int ncol = C0 + np * 16;
            uint32_t b0, b1, b2, b3;
            LDSM4(b0, b1, b2, b3,
                  bBase + (uint32_t)(((ncol + brow_in) * SPAD + k0 + bcolh) * 2));
            MMA16816F16(acc[2 * np],     a0, a1, a2, a3, b0, b1);
            MMA16816F16(acc[2 * np + 1], a0, a1, a2, a3, b2, b3);
        }
    }

    // ---- Epilogue: accum regs -> g_support as fp16 (half2 per 2 cols) ----
    const int g   = lane >> 2;
    const int tig = lane & 3;
    const int m1  = m0 + R + g;
    const int m2  = m1 + 8;
    #pragma unroll
    for (int nt = 0; nt < 8; nt++) {
        const int c = C0 + nt * 8 + tig * 2;
        if (m1 < N_NODES)
            *(__half2*)&g_support[(size_t)m1 * F + c] = __floats2half2_rn(acc[nt][0], acc[nt][1]);
        if (m2 < N_NODES)
            *(__half2*)&g_support[(size_t)m2 * F + c] = __floats2half2_rn(acc[nt][2], acc[nt][3]);
    }
}

// ---------------------------------------------------------------------------
// Kernel 0: W^T fp16 convert (tiny; runs before/with everything else)
// ---------------------------------------------------------------------------
__global__ void prep_w_kernel(const float* __restrict__ w) {
    int i = blockIdx.x * blockDim.x + threadIdx.x;   // i = n*F + k
    if (i >= F * F) return;
    int n = i >> 7, k = i & 127;
    g_wt[i] = __float2half(w[k * F + n]);
}

// ---------------------------------------------------------------------------
// Kernel 2: single-pass exclusive scan of g_count -> g_start
// 49 co-resident blocks; decoupled lookback, full-predecessor stride.
// ---------------------------------------------------------------------------
__global__ __launch_bounds__(1024) void scan_fused_kernel() {
    __shared__ int wsum[32];
    __shared__ int blk_prev;
    const int t    = threadIdx.x;
    const int bid  = blockIdx.x;
    const int lane = t & 31;
    const int wid  = t >> 5;
    const int idx  = bid * 1024 + t;

    const int v = (idx < N_NODES) ? g_count[idx] : 0;

    int s = v;
    #pragma unroll
    for (int off = 1; off < 32; off <<= 1) {
        int n = __shfl_up_sync(0xffffffffu, s, off);
        if (lane >= off) s += n;
    }
    if (lane == 31) wsum[wid] = s;
    __syncthreads();

    if (wid == 0) {
        int ws = wsum[lane];
        #pragma unroll
        for (int off = 1; off < 32; off <<= 1) {
            int n = __shfl_up_sync(0xffffffffu, ws, off);
            if (lane >= off) ws += n;
        }
        wsum[lane] = ws;
        if (lane == 31) atomicExch(&g_agg[bid], ws | AGG_FLAG);

        int a = 0;
        for (int p = lane; p < bid; p += 32) {
            volatile int* agg = g_agg;
            int xv;
            do { xv = agg[p]; } while (!(xv & AGG_FLAG));
            a += xv & (AGG_FLAG - 1);
        }
        #pragma unroll
        for (int off = 16; off >= 1; off >>= 1)
            a += __shfl_xor_sync(0xffffffffu, a, off);
        if (lane == 0) blk_prev = a;
    }
    __syncthreads();

    const int wexcl = (wid > 0) ? wsum[wid - 1] : 0;
    if (idx < N_NODES) g_start[idx] = blk_prev + wexcl + (s - v);
    if (idx == 0) g_start[N_NODES] = N_EDGES;
}

// ---------------------------------------------------------------------------
// Kernel 3: scatter edges into CSR order (atomicSub cursor -> back to 0)
// ---------------------------------------------------------------------------
__global__ void scatter_kernel(const int*   __restrict__ rows,
                               const int*   __restrict__ cols,
                               const float* __restrict__ vals) {
    int e = blockIdx.x * blockDim.x + threadIdx.x;
    if (e >= N_EDGES) return;
    int r = rows[e];
    int p = g_start[r] + atomicSub(&g_count[r], 1) - 1;
    g_edge[p] = make_int2(cols[e], __float_as_int(vals[e]));
}

// ---------------------------------------------------------------------------
// Kernel 4: CSR SpMM (R11 version — measured best): warp per row, 4-edge ILP,
// fp16 gathers (uint2 per lane), fp32 accumulation, bias fused, atomic-free.
// ---------------------------------------------------------------------------
__device__ __forceinline__ void fma_half4(float4& acc, float v, uint2 u) {
    const float2 f0 = __half22float2(*reinterpret_cast<__half2*>(&u.x));
    const float2 f1 = __half22float2(*reinterpret_cast<__half2*>(&u.y));
    acc.x += v * f0.x; acc.y += v * f0.y;
    acc.z += v * f1.x; acc.w += v * f1.y;
}

__global__ __launch_bounds__(256) void spmm_csr_kernel(const float* __restrict__ bias,
                                                       float*       __restrict__ out) {
    const int warp = (blockIdx.x * blockDim.x + threadIdx.x) >> 5;
    const int lane = threadIdx.x & 31;
    if (warp >= N_NODES) return;

    const int s = g_start[warp];
    const int e = g_start[warp + 1];

    float4 acc = ((const float4*)bias)[lane];

    int base = s;
    for (; base + 4 <= e; base += 4) {
        const int2 e0 = g_edge[base + 0];
        const int2 e1 = g_edge[base + 1];
        const int2 e2 = g_edge[base + 2];
        const int2 e3 = g_edge[base + 3];
        const uint2 u0 = *(const uint2*)&g_support[(size_t)e0.x * F + lane * 4];
        const uint2 u1 = *(const uint2*)&g_support[(size_t)e1.x * F + lane * 4];
        const uint2 u2 = *(const uint2*)&g_support[(size_t)e2.x * F + lane * 4];
        const uint2 u3 = *(const uint2*)&g_support[(size_t)e3.x * F + lane * 4];
        fma_half4(acc, __int_as_float(e0.y), u0);
        fma_half4(acc, __int_as_float(e1.y), u1);
        fma_half4(acc, __int_as_float(e2.y), u2);
        fma_half4(acc, __int_as_float(e3.y), u3);
    }
    for (; base < e; base++) {
        const int2  ed = g_edge[base];
        const uint2 u  = *(const uint2*)&g_support[(size_t)ed.x * F + lane * 4];
        fma_half4(acc, __int_as_float(ed.y), u);
    }

    *(float4*)&out[(size_t)warp * F + lane * 4] = acc;
}

// ---------------------------------------------------------------------------
// Launch. Inputs: 0=x, 1=weight, 2=bias, 3=edge_vals, 4=edge_rows, 5=edge_cols
// ---------------------------------------------------------------------------
extern "C" void kernel_launch(void* const* d_in, const int* in_sizes, int n_in,
                              void* d_out, int out_size) {
    const float* x    = (const float*)d_in[0];
    const float* w    = (const float*)d_in[1];
    const float* bias = (const float*)d_in[2];
    const float* vals = (const float*)d_in[3];
    const int*   rows = (const int*)d_in[4];
    const int*   cols = (const int*)d_in[5];
    float*       out  = (float*)d_out;

    static bool attr_set = false;
    if (!attr_set) {
        cudaFuncSetAttribute(gemm_hist_kernel,
                             cudaFuncAttributeMaxDynamicSharedMemorySize, GEMM_SMEM);
        attr_set = true;
    }

    // 0) W^T -> fp16 (tiny)
    prep_w_kernel<<<(F * F + 255) / 256, 256>>>(w);
    // 1) GEMM (support = x @ W, fp16) + fused histogram + flag reset
    gemm_hist_kernel<<<GEMM_BLOCKS, GEMM_THREADS, GEMM_SMEM>>>(x, rows);
    // 2) single-pass scan -> g_start
    scan_fused_kernel<<<SCAN_BLOCKS, 1024>>>();
    // 3) scatter into CSR order (cursor decrements back to 0)
    scatter_kernel<<<(N_EDGES + 255) / 256, 256>>>(rows, cols, vals);
    // 4) out = A_csr @ support + bias
    {
        const long long threads = (long long)N_NODES * 32;
        spmm_csr_kernel<<<(int)((threads + 255) / 256), 256>>>(bias, out);
    }
}